// round 17
// baseline (speedup 1.0000x reference)
#include <cuda_runtime.h>
#include <cuda_bf16.h>

// CBOW negative-sampling loss — dual-path gather, 2-task double-buffered.
//   i_emb (ctx rows)  -> LDG path (L1tex miss pool)
//   o_emb (tgt+neg)   -> cp.async.bulk path (TMA queue) into SMEM
// Each warp owns 2 batch rows: both tasks' 22 bulk copies are issued up
// front (2 mbarriers / 2 stage buffers), then both tasks' 20 ctx LDGs,
// then wait+compute task0, wait+compute task1. Doubles bulk-path
// bytes-in-flight per warp vs R15 and hides the mbarrier wait.
//
// Inputs (metadata order):
//   d_in[0] i_emb f32 (VOCAB+1,50) | d_in[1] o_emb f32 (VOCAB+1,50)
//   d_in[2] target (B,) | d_in[3] context (B,10) | d_in[4] neg (B,10)
// Output: scalar f32 = -( sum log_sigmoid(pos) + sum log_sigmoid(-neg) )
//
// Rows are 200 B at 8B alignment; bulk copies fetch the 16B-aligned 224 B
// window (same DRAM sectors); SMEM read offset = off & 15. The (VOCAB+1)
// spare row keeps the window in-bounds for all wids < VOCAB.

#define DIM2  25
#define CTX   10
#define NNEG  10
#define OSLOT 11      // 1 target + 10 neg per task
#define ROWB  200u
#define SLOTB 224
#define MAX_BLOCKS 8192

__device__ float        g_partials[MAX_BLOCKS];
__device__ unsigned int g_count = 0;   // reset by last block each launch

__device__ __forceinline__ float log_sigmoid(float x) {
    return fminf(x, 0.0f) - __logf(1.0f + __expf(-fabsf(x)));
}

__device__ __forceinline__ void mbar_init(unsigned mbar, unsigned cnt) {
    asm volatile("mbarrier.init.shared.b64 [%0], %1;" :: "r"(mbar), "r"(cnt) : "memory");
}
__device__ __forceinline__ void mbar_expect_tx(unsigned mbar, unsigned bytes) {
    asm volatile("mbarrier.arrive.expect_tx.shared.b64 _, [%0], %1;"
                 :: "r"(mbar), "r"(bytes) : "memory");
}
__device__ __forceinline__ void mbar_wait(unsigned mbar, unsigned parity) {
    asm volatile(
        "{\n\t.reg .pred P;\n"
        "W%=:\n\t"
        "mbarrier.try_wait.parity.shared.b64 P, [%0], %1;\n\t"
        "@!P bra W%=;\n\t}"
        :: "r"(mbar), "r"(parity) : "memory");
}
__device__ __forceinline__ void bulk_cp(unsigned dst, const void* src,
                                        unsigned bytes, unsigned mbar) {
    asm volatile(
        "cp.async.bulk.shared::cluster.global.mbarrier::complete_tx::bytes "
        "[%0], [%1], %2, [%3];"
        :: "r"(dst), "l"(src), "r"(bytes), "r"(mbar) : "memory");
}
__device__ __forceinline__ float2 lds64(unsigned addr) {
    float2 r;
    asm volatile("ld.shared.v2.f32 {%0,%1}, [%2];"
                 : "=f"(r.x), "=f"(r.y) : "r"(addr));
    return r;
}

// 5-shfl pairwise warp reduction: lane 0 gets sum(A), lane 16 gets sum(B).
__device__ __forceinline__ float pair_reduce(float A, float B, int lane) {
    float x = (lane & 16) ? A : B;
    float y = __shfl_xor_sync(0xFFFFFFFFu, x, 16);
    float v = ((lane & 16) ? B : A) + y;
    v += __shfl_xor_sync(0xFFFFFFFFu, v, 8);
    v += __shfl_xor_sync(0xFFFFFFFFu, v, 4);
    v += __shfl_xor_sync(0xFFFFFFFFu, v, 2);
    v += __shfl_xor_sync(0xFFFFFFFFu, v, 1);
    return v;
}

// Score one task from its SMEM stage: 11 dot products + reductions.
__device__ __forceinline__ float score_task(
    unsigned sb, const unsigned* inoff, float ax, float ay, int lane)
{
    float p[OSLOT];
    #pragma unroll
    for (int k = 0; k < OSLOT; k++) p[k] = 0.0f;

    if (lane < DIM2) {
        const unsigned le = lane * 8;
        #pragma unroll
        for (int s = 0; s < OSLOT; s++) {
            const float2 e = lds64(sb + s * SLOTB + inoff[s] + le);
            p[s] = e.x * ax + e.y * ay;
        }
    }

    const float inv_ctx = 1.0f / CTX;
    float loss = 0.0f;

    // pair 0: (pos, neg0) — mixed signs
    {
        float v = pair_reduce(p[0], p[1], lane);
        if ((lane & 15) == 0) {
            float sc = v * inv_ctx;
            loss += log_sigmoid((lane & 16) ? -sc : sc);
        }
    }
    #pragma unroll
    for (int k = 2; k <= 8; k += 2) {
        float v = pair_reduce(p[k], p[k + 1], lane);
        if ((lane & 15) == 0)
            loss += log_sigmoid(-v * inv_ctx);
    }
    {   // leftover neg9
        float v = p[10];
        #pragma unroll
        for (int o = 16; o > 0; o >>= 1)
            v += __shfl_xor_sync(0xFFFFFFFFu, v, o);
        if (lane == 0)
            loss += log_sigmoid(-v * inv_ctx);
    }
    return loss;
}

__global__ void __launch_bounds__(256) cbow_pipe_kernel(
    const float* __restrict__ i_emb,
    const float* __restrict__ o_emb,
    const int*   __restrict__ target_wids,
    const int*   __restrict__ context_wids,
    const int*   __restrict__ neg_wids,
    float*       __restrict__ out,
    int B)
{
    __shared__ __align__(16) char stage[8][2][OSLOT * SLOTB];   // 39424 B
    __shared__ __align__(8)  unsigned long long mbar[8][2];
    __shared__ float  s_partial[8];
    __shared__ int    s_is_last;
    __shared__ double s_d[8];

    const int warp_global = (blockIdx.x * blockDim.x + threadIdx.x) >> 5;
    const int lane        = threadIdx.x & 31;
    const int warp_local  = threadIdx.x >> 5;

    float loss = 0.0f;

    const int t0 = warp_global * 2;
    const int t1 = t0 + 1;

    if (t0 < B) {
        const bool  has1 = (t1 < B);
        const float2* __restrict__ i2 = (const float2*)i_emb;
        const char*   __restrict__ ob = (const char*)o_emb;

        const unsigned sb0 = (unsigned)__cvta_generic_to_shared(stage[warp_local][0]);
        const unsigned sb1 = (unsigned)__cvta_generic_to_shared(stage[warp_local][1]);
        const unsigned mb0 = (unsigned)__cvta_generic_to_shared(&mbar[warp_local][0]);
        const unsigned mb1 = (unsigned)__cvta_generic_to_shared(&mbar[warp_local][1]);

        // ---- mbarrier setup (each used once per launch; parity 0) ----
        if (lane == 0) {
            mbar_init(mb0, 1);
            mbar_init(mb1, 1);
            asm volatile("fence.proxy.async.shared::cta;" ::: "memory");
            mbar_expect_tx(mb0, OSLOT * SLOTB);
            if (has1) mbar_expect_tx(mb1, OSLOT * SLOTB);
        }
        __syncwarp();

        // ---- issue ALL bulk copies for both tasks (22 in flight) ----
        unsigned ooff0 = 0, ooff1 = 0;
        if (lane < OSLOT) {
            int idx0 = (lane == 0) ? __ldg(&target_wids[t0])
                                   : __ldg(&neg_wids[t0 * NNEG + lane - 1]);
            ooff0 = (unsigned)idx0 * ROWB;
            bulk_cp(sb0 + lane * SLOTB, ob + (ooff0 & ~15u), SLOTB, mb0);
            if (has1) {
                int idx1 = (lane == 0) ? __ldg(&target_wids[t1])
                                       : __ldg(&neg_wids[t1 * NNEG + lane - 1]);
                ooff1 = (unsigned)idx1 * ROWB;
                bulk_cp(sb1 + lane * SLOTB, ob + (ooff1 & ~15u), SLOTB, mb1);
            }
        }

        // ---- ctx LDGs for both tasks (20 lines in flight, overlaps bulk)
        int cb0[CTX], cb1[CTX];
        #pragma unroll
        for (int c = 0; c < CTX; c++) {
            cb0[c] = __ldg(&context_wids[t0 * CTX + c]) * DIM2;
            cb1[c] = has1 ? __ldg(&context_wids[t1 * CTX + c]) * DIM2 : 0;
        }

        float ax0 = 0.0f, ay0 = 0.0f, ax1 = 0.0f, ay1 = 0.0f;
        if (lane < DIM2) {
            #pragma unroll
            for (int c = 0; c < CTX; c++) {
                const float2 e0 = __ldg(&i2[cb0[c] + lane]);
                ax0 += e0.x;  ay0 += e0.y;
            }
            if (has1) {
                #pragma unroll
                for (int c = 0; c < CTX; c++) {
                    const float2 e1 = __ldg(&i2[cb1[c] + lane]);
                    ax1 += e1.x;  ay1 += e1.y;
                }
            }
        }

        // broadcast per-slot in-slot offsets to the whole warp
        unsigned inoff0[OSLOT], inoff1[OSLOT];
        #pragma unroll
        for (int s = 0; s < OSLOT; s++) {
            inoff0[s] = __shfl_sync(0xFFFFFFFFu, ooff0 & 15u, s);
            inoff1[s] = __shfl_sync(0xFFFFFFFFu, ooff1 & 15u, s);
        }

        // ---- task 0: wait + score ----
        mbar_wait(mb0, 0);
        loss += score_task(sb0, inoff0, ax0, ay0, lane);

        // ---- task 1: wait + score ----
        if (has1) {
            mbar_wait(mb1, 0);
            loss += score_task(sb1, inoff1, ax1, ay1, lane);
        }
    }

    // combine lanes 0 and 16
    loss += __shfl_xor_sync(0xFFFFFFFFu, loss, 16);
    if (lane == 0) s_partial[warp_local] = loss;
    __syncthreads();

    // block partial + last-block ticket
    if (threadIdx.x == 0) {
        float blk = 0.0f;
        #pragma unroll
        for (int i = 0; i < 8; i++) blk += s_partial[i];
        g_partials[blockIdx.x] = blk;
        __threadfence();
        unsigned int old = atomicAdd(&g_count, 1u);
        s_is_last = (old == gridDim.x - 1);
    }
    __syncthreads();

    if (s_is_last) {
        const int nb2 = gridDim.x;
        volatile float* vp = g_partials;
        double acc = 0.0;
        for (int i = threadIdx.x; i < nb2; i += 256)
            acc += (double)vp[i];
        #pragma unroll
        for (int o = 16; o > 0; o >>= 1)
            acc += __shfl_xor_sync(0xFFFFFFFFu, acc, o);
        if ((threadIdx.x & 31) == 0) s_d[threadIdx.x >> 5] = acc;
        __syncthreads();
        if (threadIdx.x == 0) {
            double t = 0.0;
            #pragma unroll
            for (int i = 0; i < 8; i++) t += s_d[i];
            out[0] = (float)(-t);
            g_count = 0;
        }
    }
}

extern "C" void kernel_launch(void* const* d_in, const int* in_sizes, int n_in,
                              void* d_out, int out_size)
{
    const float* i_emb        = (const float*)d_in[0];
    const float* o_emb        = (const float*)d_in[1];
    const int*   target_wids  = (const int*)d_in[2];
    const int*   context_wids = (const int*)d_in[3];
    const int*   neg_wids     = (const int*)d_in[4];
    float*       out          = (float*)d_out;

    const int B = in_sizes[2];
    const int rows_per_block = 8 * 2;       // 8 warps x 2 tasks
    int blocks = (B + rows_per_block - 1) / rows_per_block;
    if (blocks > MAX_BLOCKS) blocks = MAX_BLOCKS;   // B=16384 -> 1024

    cbow_pipe_kernel<<<blocks, 256>>>(i_emb, o_emb, target_wids,
                                      context_wids, neg_wids, out, B);
}